// round 2
// baseline (speedup 1.0000x reference)
#include <cuda_runtime.h>

// MeantimeMultiHeadAttention — restructured:
//  u[b,q]   = Wk_h · q_h          (rel score becomes a 128-dot per (q,k))
//  w[b,q]   = sum_k p[k] rel[q,k] (rel ctx becomes one 128x32 matmul per (b,q))
//  Keff/Veff fold abs-head projections; bk-constant terms cancel in softmax.

#define Bz  8
#define Sz  256
#define Hz  128
#define HDz 32
#define BSz 2048
#define SCALE 0.17677669529663687f   // 1/sqrt(32)
#define TSTRIDE 132                   // 128 + 4 pad: 528B rows, 16B aligned, conflict-free phases

// Scratch (allocation-free rule: __device__ globals)
__device__ float g_Q[BSz * Hz];
__device__ float g_Keff[BSz * Hz];
__device__ float g_Veff[BSz * Hz];
__device__ float g_u[BSz * 2 * Hz];
__device__ float g_ctx[BSz * Hz];

// ---------------------------------------------------------------------------
// Kernel A: projections. One CTA per (b,s) row, 128 threads.
//   Q = X Wq + bq
//   Keff = X Wk + bk  (+ abs_h Wk_h + bk_h for head slices h<2)
//   Veff = X Wv + bv  (+ abs_h Wv_h + bv_h for head slices h<2)
//   u_i[j] = sum_c Wk[j, (2+i)*32+c] * Q[b,s,(2+i)*32+c]
// ---------------------------------------------------------------------------
__global__ void proj_kernel(const float* __restrict__ X,
                            const float* __restrict__ abs0,
                            const float* __restrict__ abs1,
                            const float* __restrict__ Wq, const float* __restrict__ bq,
                            const float* __restrict__ Wk, const float* __restrict__ bk,
                            const float* __restrict__ Wv, const float* __restrict__ bv) {
    int row = blockIdx.x;       // 0..2047
    int j   = threadIdx.x;      // 0..127
    __shared__ float xs[Hz], a0[Hz], a1[Hz], qs[Hz];
    xs[j] = X[row * Hz + j];
    a0[j] = abs0[row * Hz + j];
    a1[j] = abs1[row * Hz + j];
    __syncthreads();

    float q = bq[j], k = bk[j], v = bv[j];
    #pragma unroll 8
    for (int i = 0; i < Hz; i++) {
        float xi = xs[i];
        q += xi * Wq[i * Hz + j];
        k += xi * Wk[i * Hz + j];
        v += xi * Wv[i * Hz + j];
    }
    if (j < 64) {  // abs-head key/value folds (head h = j>>5)
        const float* a = (j < 32) ? a0 : a1;
        float ka = bk[j], va = bv[j];
        #pragma unroll 8
        for (int i = 0; i < Hz; i++) {
            float ai = a[i];
            ka += ai * Wk[i * Hz + j];
            va += ai * Wv[i * Hz + j];
        }
        k += ka; v += va;
    }
    g_Q[row * Hz + j]    = q;  qs[j] = q;
    g_Keff[row * Hz + j] = k;
    g_Veff[row * Hz + j] = v;
    __syncthreads();

    #pragma unroll
    for (int i = 0; i < 2; i++) {
        int base = (2 + i) * HDz;
        float acc = 0.f;
        #pragma unroll 8
        for (int c = 0; c < HDz; c++)
            acc += Wk[j * Hz + base + c] * qs[base + c];
        g_u[(row * 2 + i) * Hz + j] = acc;
    }
}

// ---------------------------------------------------------------------------
// Kernel B: abs heads (h = 0,1). One CTA per (b,h,q), 256 threads (thread = k).
// ---------------------------------------------------------------------------
__global__ void abs_attn_kernel(const float* __restrict__ mask) {
    int q = blockIdx.x, b = blockIdx.y, h = blockIdx.z;
    int t = threadIdx.x, lane = t & 31, wid = t >> 5;
    __shared__ float qv[HDz];
    __shared__ float sc[Sz];
    __shared__ float red[8];
    __shared__ float bcast[2];
    __shared__ float part[8 * HDz];

    if (t < HDz) qv[t] = g_Q[(b * Sz + q) * Hz + h * HDz + t];
    __syncthreads();

    const float4* Kp = (const float4*)&g_Keff[(b * Sz + t) * Hz + h * HDz];
    float acc = 0.f;
    #pragma unroll
    for (int jj = 0; jj < 8; jj++) {
        float4 kk = Kp[jj];
        acc += kk.x * qv[4*jj] + kk.y * qv[4*jj+1] + kk.z * qv[4*jj+2] + kk.w * qv[4*jj+3];
    }
    float s = acc * SCALE + mask[(b * Sz + q) * Sz + t];

    // softmax (max)
    float m = s;
    #pragma unroll
    for (int o = 16; o; o >>= 1) m = fmaxf(m, __shfl_xor_sync(0xffffffffu, m, o));
    if (lane == 0) red[wid] = m;
    __syncthreads();
    if (t == 0) { float mm = red[0]; for (int w = 1; w < 8; w++) mm = fmaxf(mm, red[w]); bcast[0] = mm; }
    __syncthreads();
    m = bcast[0];
    float p = __expf(s - m);
    sc[t] = p;
    float su = p;
    #pragma unroll
    for (int o = 16; o; o >>= 1) su += __shfl_xor_sync(0xffffffffu, su, o);
    if (lane == 0) red[wid] = su;
    __syncthreads();
    if (t == 0) { float ss = 0.f; for (int w = 0; w < 8; w++) ss += red[w]; bcast[1] = 1.f / ss; }
    __syncthreads();
    float inv = bcast[1];

    // ctx = P * Veff  (8 k-slices per output channel)
    int c = t & 31, sl = t >> 5;
    float a = 0.f;
    #pragma unroll 8
    for (int kk = 0; kk < 32; kk++) {
        int k = sl * 32 + kk;
        a += sc[k] * g_Veff[(b * Sz + k) * Hz + h * HDz + c];
    }
    part[t] = a;
    __syncthreads();
    if (t < HDz) {
        float o2 = 0.f;
        #pragma unroll
        for (int s2 = 0; s2 < 8; s2++) o2 += part[s2 * HDz + t];
        g_ctx[(b * Sz + q) * Hz + h * HDz + t] = o2 * inv;
    }
}

// ---------------------------------------------------------------------------
// Kernel C: rel heads (h = 2,3). One CTA per (b,i,q), 256 threads.
// Stages rel[b,q] (256x128 fl, 128KB) in smem; reads it ONCE from HBM,
// twice from smem (score dots, then probability-weighted channel sums).
// ---------------------------------------------------------------------------
__global__ void __launch_bounds__(256) rel_attn_kernel(
        const float* __restrict__ rel0, const float* __restrict__ rel1,
        const float* __restrict__ mask,
        const float* __restrict__ Wv, const float* __restrict__ bv) {
    int q = blockIdx.x, b = blockIdx.y, i = blockIdx.z;
    int h = 2 + i;
    int t = threadIdx.x, lane = t & 31, wid = t >> 5;

    extern __shared__ float smem[];
    float* tile  = smem;                    // [256][132]
    float* uvec  = tile + Sz * TSTRIDE;     // 128
    float* qv    = uvec + Hz;               // 32
    float* sc    = qv + HDz;                // 256 (scores -> probs)
    float* red   = sc + Sz;                 // 8
    float* bcast = red + 8;                 // 2
    float* wpart = bcast + 8;               // 256 (padded start)
    float* wfin  = wpart + Sz;              // 128
    float* part  = wfin + Hz;               // 256

    // small vectors
    const float* ub = &g_u[((size_t)(b * Sz + q) * 2 + i) * Hz];
    if (t < Hz)            uvec[t] = ub[t];
    else if (t < Hz + HDz) qv[t - Hz] = g_Q[(b * Sz + q) * Hz + h * HDz + (t - Hz)];

    // stream rel tile HBM -> smem (float4, coalesced; 16B-aligned smem rows)
    const float* relbase = (i == 0 ? rel0 : rel1);
    const float4* rp = (const float4*)(relbase + (size_t)(b * Sz + q) * Sz * Hz);
    #pragma unroll
    for (int it = 0; it < 32; it++) {
        int idx = t + it * 256;
        int k = idx >> 5, c4 = idx & 31;
        float4 v4 = rp[idx];
        *(float4*)&tile[k * TSTRIDE + c4 * 4] = v4;
    }
    __syncthreads();

    // Phase A: scores. thread t = key index k.
    float acc = 0.f;
    {
        const float4* rowp = (const float4*)&tile[t * TSTRIDE];
        #pragma unroll
        for (int jj = 0; jj < 32; jj++) {
            float4 r = rowp[jj];
            acc += r.x * uvec[4*jj] + r.y * uvec[4*jj+1] + r.z * uvec[4*jj+2] + r.w * uvec[4*jj+3];
        }
        const float4* Kp = (const float4*)&g_Keff[(b * Sz + t) * Hz + h * HDz];
        #pragma unroll
        for (int jj = 0; jj < 8; jj++) {
            float4 kk = Kp[jj];
            acc += kk.x * qv[4*jj] + kk.y * qv[4*jj+1] + kk.z * qv[4*jj+2] + kk.w * qv[4*jj+3];
        }
    }
    float s = acc * SCALE + mask[(b * Sz + q) * Sz + t];

    // softmax over 256
    float m = s;
    #pragma unroll
    for (int o = 16; o; o >>= 1) m = fmaxf(m, __shfl_xor_sync(0xffffffffu, m, o));
    if (lane == 0) red[wid] = m;
    __syncthreads();
    if (t == 0) { float mm = red[0]; for (int w = 1; w < 8; w++) mm = fmaxf(mm, red[w]); bcast[0] = mm; }
    __syncthreads();
    m = bcast[0];
    float p = __expf(s - m);
    sc[t] = p;
    float su = p;
    #pragma unroll
    for (int o = 16; o; o >>= 1) su += __shfl_xor_sync(0xffffffffu, su, o);
    if (lane == 0) red[wid] = su;
    __syncthreads();
    if (t == 0) { float ss = 0.f; for (int w = 0; w < 8; w++) ss += red[w]; bcast[1] = 1.f / ss; }
    __syncthreads();
    float inv = bcast[1];

    // Phase B: w[ch] = sum_k p[k] * rel[k][ch]   (2 threads per ch, k halves)
    {
        int ch = t & 127, half = t >> 7;
        float wacc = 0.f;
        const float* col = &tile[half * 128 * TSTRIDE + ch];
        const float* pw  = &sc[half * 128];
        #pragma unroll 8
        for (int kk = 0; kk < 128; kk++)
            wacc += pw[kk] * col[kk * TSTRIDE];
        wpart[t] = wacc;
    }

    // ctxV = sum_k p[k] * V_h[b,k,:]
    {
        int c = t & 31, sl = t >> 5;
        float a = 0.f;
        #pragma unroll 8
        for (int kk = 0; kk < 32; kk++) {
            int k = sl * 32 + kk;
            a += sc[k] * g_Veff[(b * Sz + k) * Hz + h * HDz + c];
        }
        part[t] = a;
    }
    __syncthreads();
    if (t < Hz) wfin[t] = wpart[t] + wpart[t + 128];
    __syncthreads();

    if (t < HDz) {
        float o2 = 0.f;
        #pragma unroll
        for (int s2 = 0; s2 < 8; s2++) o2 += part[s2 * HDz + t];
        float wo = 0.f;
        #pragma unroll 8
        for (int ch = 0; ch < Hz; ch++)
            wo += wfin[ch] * Wv[ch * Hz + h * HDz + t];
        g_ctx[(b * Sz + q) * Hz + h * HDz + t] = (o2 + wo) * inv + bv[h * HDz + t];
    }
}

// ---------------------------------------------------------------------------
// Kernel D: out = ctx @ Wo + bo
// ---------------------------------------------------------------------------
__global__ void out_proj_kernel(const float* __restrict__ Wo,
                                const float* __restrict__ bo,
                                float* __restrict__ out) {
    int row = blockIdx.x;
    int j = threadIdx.x;
    __shared__ float xs[Hz];
    xs[j] = g_ctx[row * Hz + j];
    __syncthreads();
    float acc = bo[j];
    #pragma unroll 8
    for (int i = 0; i < Hz; i++)
        acc += xs[i] * Wo[i * Hz + j];
    out[row * Hz + j] = acc;
}

// ---------------------------------------------------------------------------
extern "C" void kernel_launch(void* const* d_in, const int* in_sizes, int n_in,
                              void* d_out, int out_size) {
    const float* X    = (const float*)d_in[0];
    const float* mask = (const float*)d_in[1];
    const float* abs0 = (const float*)d_in[2];
    const float* abs1 = (const float*)d_in[3];
    const float* rel0 = (const float*)d_in[4];
    const float* rel1 = (const float*)d_in[5];
    const float* Wq   = (const float*)d_in[6];
    const float* bq   = (const float*)d_in[7];
    const float* Wk   = (const float*)d_in[8];
    const float* bk   = (const float*)d_in[9];
    const float* Wv   = (const float*)d_in[10];
    const float* bv   = (const float*)d_in[11];
    const float* Wo   = (const float*)d_in[12];
    const float* bo   = (const float*)d_in[13];
    float* out = (float*)d_out;

    size_t smem_bytes = (size_t)(Sz * TSTRIDE + Hz + HDz + Sz + 8 + 8 + Sz + Hz + Sz) * sizeof(float);
    cudaFuncSetAttribute(rel_attn_kernel, cudaFuncAttributeMaxDynamicSharedMemorySize,
                         (int)smem_bytes);

    proj_kernel<<<BSz, Hz>>>(X, abs0, abs1, Wq, bq, Wk, bk, Wv, bv);
    dim3 g(Sz, Bz, 2);
    abs_attn_kernel<<<g, 256>>>(mask);
    rel_attn_kernel<<<g, 256, smem_bytes>>>(rel0, rel1, mask, Wv, bv);
    out_proj_kernel<<<BSz, Hz>>>(Wo, bo, out);
}

// round 4
// speedup vs baseline: 1.7588x; 1.7588x over previous
#include <cuda_runtime.h>
#include <cstdint>

#define Bz  8
#define Sz  256
#define Hz  128
#define HDz 32
#define BSz 2048
#define SCALE 0.17677669529663687f   // 1/sqrt(32)
#define TST 132                       // rel tile row stride (floats)
#define CK  64                        // keys per chunk
#define NCH 4                         // chunks per (b,q)

// __device__ scratch (allocation-free rule)
__device__ float g_Q[BSz * Hz];
__device__ float g_Keff[BSz * Hz];
__device__ float g_Veff[BSz * Hz];
__device__ float g_sbase[Bz * 4 * Sz * Sz];   // [b][h][q][k], 8 MB
__device__ float g_probs[Bz * 4 * Sz * Sz];   // normalized probs, 8 MB
__device__ float g_ctxbase[BSz * Hz];
__device__ float g_ctx[BSz * Hz];

#define CP_ASYNC16(dst, src) \
    asm volatile("cp.async.cg.shared.global [%0], [%1], 16;\n" :: "r"(dst), "l"(src))
#define CP_COMMIT() asm volatile("cp.async.commit_group;\n" ::: "memory")
#define CP_WAIT1()  asm volatile("cp.async.wait_group 1;\n" ::: "memory")
#define CP_WAIT0()  asm volatile("cp.async.wait_group 0;\n" ::: "memory")

// ---------------------------------------------------------------------------
// K0: projections. 2 rows per CTA, 128 threads.
// ---------------------------------------------------------------------------
__global__ void proj_kernel(const float* __restrict__ X,
                            const float* __restrict__ abs0,
                            const float* __restrict__ abs1,
                            const float* __restrict__ Wq, const float* __restrict__ bq,
                            const float* __restrict__ Wk, const float* __restrict__ bk,
                            const float* __restrict__ Wv, const float* __restrict__ bv) {
    int r0 = blockIdx.x * 2;
    int j  = threadIdx.x;
    __shared__ float xs[2][Hz], a0s[2][Hz], a1s[2][Hz];
    #pragma unroll
    for (int r = 0; r < 2; r++) {
        xs[r][j]  = X[(r0 + r) * Hz + j];
        a0s[r][j] = abs0[(r0 + r) * Hz + j];
        a1s[r][j] = abs1[(r0 + r) * Hz + j];
    }
    __syncthreads();

    float q0 = bq[j], k0 = bk[j], v0 = bv[j];
    float q1 = q0, k1 = k0, v1 = v0;
    #pragma unroll 4
    for (int i = 0; i < Hz; i++) {
        float wq = Wq[i * Hz + j], wk = Wk[i * Hz + j], wv = Wv[i * Hz + j];
        float x0 = xs[0][i], x1 = xs[1][i];
        q0 += x0 * wq; k0 += x0 * wk; v0 += x0 * wv;
        q1 += x1 * wq; k1 += x1 * wk; v1 += x1 * wv;
    }
    if (j < 64) {   // abs-head folds (head = j>>5); extra bk/bv consts cancel/are exact
        float ka0 = bk[j], va0 = bv[j], ka1 = ka0, va1 = va0;
        #pragma unroll 4
        for (int i = 0; i < Hz; i++) {
            float wk = Wk[i * Hz + j], wv = Wv[i * Hz + j];
            float b0 = (j < 32) ? a0s[0][i] : a1s[0][i];
            float b1 = (j < 32) ? a0s[1][i] : a1s[1][i];
            ka0 += b0 * wk; va0 += b0 * wv;
            ka1 += b1 * wk; va1 += b1 * wv;
        }
        k0 += ka0; v0 += va0; k1 += ka1; v1 += va1;
    }
    g_Q[r0 * Hz + j] = q0;        g_Q[(r0 + 1) * Hz + j] = q1;
    g_Keff[r0 * Hz + j] = k0;     g_Keff[(r0 + 1) * Hz + j] = k1;
    g_Veff[r0 * Hz + j] = v0;     g_Veff[(r0 + 1) * Hz + j] = v1;
}

// ---------------------------------------------------------------------------
// K1: sbase[b,h,q,k] = (Q_h[q] . Keff_h[k]) * SCALE + mask[b,q,k]
// grid (qt=8, b=8, h=4), 256 threads (thread = k), 32 q per CTA.
// ---------------------------------------------------------------------------
__global__ void __launch_bounds__(256) sbase_kernel(const float* __restrict__ mask) {
    int qt = blockIdx.x, b = blockIdx.y, h = blockIdx.z;
    int t = threadIdx.x;
    __shared__ float Qs[32 * 32];
    __shared__ float ks[256 * 33];

    #pragma unroll
    for (int r = 0; r < 4; r++) {
        int idx = r * 256 + t;              // 1024 floats
        int qq = idx >> 5, c = idx & 31;
        Qs[idx] = g_Q[(b * Sz + qt * 32 + qq) * Hz + h * HDz + c];
    }
    #pragma unroll
    for (int jj = 0; jj < 8; jj++) {        // 2048 float4 = 8192 floats
        int idx = jj * 256 + t;
        int row = idx >> 3, c4 = idx & 7;
        float4 v = *(const float4*)&g_Keff[(b * Sz + row) * Hz + h * HDz + c4 * 4];
        ks[row * 33 + c4 * 4 + 0] = v.x;
        ks[row * 33 + c4 * 4 + 1] = v.y;
        ks[row * 33 + c4 * 4 + 2] = v.z;
        ks[row * 33 + c4 * 4 + 3] = v.w;
    }
    __syncthreads();

    float kr[32];
    #pragma unroll
    for (int c = 0; c < 32; c++) kr[c] = ks[t * 33 + c];

    int qbase = qt * 32;
    #pragma unroll 2
    for (int qq = 0; qq < 32; qq++) {
        float acc = 0.f;
        #pragma unroll
        for (int c = 0; c < 32; c++) acc += Qs[qq * 32 + c] * kr[c];
        int q = qbase + qq;
        g_sbase[((b * 4 + h) * Sz + q) * Sz + t] =
            acc * SCALE + mask[(b * Sz + q) * Sz + t];
    }
}

// ---------------------------------------------------------------------------
// K2: rel heads. CTA per (q, b, i). Chunked double-buffered cp.async stream
// of rel[b,q] with online softmax; also finishes abs head i (softmax only).
// Outputs: g_probs (normalized, heads i and 2+i), g_ctxbase (rel w-term; abs 0).
// ---------------------------------------------------------------------------
__global__ void __launch_bounds__(256, 2) rel_kernel(
        const float* __restrict__ rel0, const float* __restrict__ rel1,
        const float* __restrict__ Wk, const float* __restrict__ Wv,
        const float* __restrict__ bv) {
    int q = blockIdx.x, b = blockIdx.y, i = blockIdx.z;
    int hr = 2 + i, ha = i;
    int t = threadIdx.x, lane = t & 31, wid = t >> 5;

    extern __shared__ float sm[];
    float* buf    = sm;                       // [2][CK*TST]
    float* kb     = sm + 2 * CK * TST;        // 256  (rel sbase row)
    float* uvec   = kb + 256;                 // 128  (u; reused as wfin)
    float* sall   = uvec + 128;               // 256  (raw rel scores)
    float* pbuf   = sall + 256;               // 64
    float* schunk = pbuf + 64;                // 64
    float* redm   = schunk + 64;              // 8
    float* bc     = redm + 8;                 // 4
    float* wpart  = bc + 4;                   // 256
    float* qvr    = wpart + 256;              // 32

    const float4* rp = (const float4*)(((i == 0) ? rel0 : rel1)
                                       + (size_t)(b * Sz + q) * Sz * Hz);
    uint32_t bufu = (uint32_t)__cvta_generic_to_shared(buf);

    // issue chunks 0,1
    #pragma unroll
    for (int ch = 0; ch < 2; ch++) {
        uint32_t bb = bufu + (uint32_t)(ch & 1) * CK * TST * 4;
        #pragma unroll
        for (int jj = 0; jj < 8; jj++) {
            int idx = jj * 256 + t;
            uint32_t d = bb + (uint32_t)((idx >> 5) * TST + (idx & 31) * 4) * 4;
            CP_ASYNC16(d, rp + ch * (CK * Hz / 4) + idx);
        }
        CP_COMMIT();
    }

    // prologue (overlaps DRAM): small vectors + abs-head softmax
    if (t < HDz) qvr[t] = g_Q[(b * Sz + q) * Hz + hr * HDz + t];
    kb[t]    = g_sbase[((b * 4 + hr) * Sz + q) * Sz + t];
    float sa = g_sbase[((b * 4 + ha) * Sz + q) * Sz + t];
    __syncthreads();

    if (t < Hz) {                      // u = Wk_hr^T qvr
        float acc = 0.f;
        const float* wrow = Wk + t * Hz + hr * HDz;
        #pragma unroll
        for (int c = 0; c < HDz; c++) acc += wrow[c] * qvr[c];
        uvec[t] = acc;
    }

    // abs softmax (thread t = key)
    {
        float m = sa;
        #pragma unroll
        for (int o = 16; o; o >>= 1) m = fmaxf(m, __shfl_xor_sync(~0u, m, o));
        if (lane == 0) redm[wid] = m;
        __syncthreads();
        if (t == 0) { float mm = redm[0]; for (int w = 1; w < 8; w++) mm = fmaxf(mm, redm[w]); bc[0] = mm; }
        __syncthreads();
        float pa = __expf(sa - bc[0]);
        float su = pa;
        #pragma unroll
        for (int o = 16; o; o >>= 1) su += __shfl_xor_sync(~0u, su, o);
        if (lane == 0) redm[wid] = su;
        __syncthreads();
        if (t == 0) { float ss = 0.f; for (int w = 0; w < 8; w++) ss += redm[w]; bc[1] = 1.f / ss; }
        __syncthreads();
        g_probs[((b * 4 + ha) * Sz + q) * Sz + t] = pa * bc[1];
        if (t < HDz) g_ctxbase[(b * Sz + q) * Hz + ha * HDz + t] = 0.f;
        __syncthreads();   // redm/bc reuse barrier
    }

    // chunk loop: online softmax + wacc
    float m = -1e30f, l = 0.f, wacc = 0.f;
    int key = t >> 2, part = t & 3;
    int chw = t & 127, half = t >> 7;

    for (int ch = 0; ch < NCH; ch++) {
        if (ch < NCH - 1) { CP_WAIT1(); } else { CP_WAIT0(); }
        __syncthreads();
        const float* cb = buf + (ch & 1) * CK * TST;

        // scores: 4 threads per key, part-interleaved (conflict-free scalar LDS)
        float a = 0.f;
        {
            const float* row = cb + key * TST + part;
            #pragma unroll
            for (int j = 0; j < 32; j++) a += row[j * 4] * uvec[j * 4 + part];
        }
        a += __shfl_xor_sync(~0u, a, 1);
        a += __shfl_xor_sync(~0u, a, 2);
        if (part == 0) schunk[key] = a * SCALE + kb[ch * CK + key];
        __syncthreads();                                   // S1

        if (t < CK) sall[ch * CK + t] = schunk[t];
        float v = schunk[t & 63];
        #pragma unroll
        for (int o = 16; o; o >>= 1) v = fmaxf(v, __shfl_xor_sync(~0u, v, o));
        if (lane == 0) redm[wid] = v;
        __syncthreads();                                   // S2
        if (t == 0) {
            float mc = redm[0];
            for (int w = 1; w < 8; w++) mc = fmaxf(mc, redm[w]);
            bc[0] = fmaxf(m, mc);
        }
        __syncthreads();                                   // S3
        float m_new = bc[0];
        float scale = __expf(m - m_new);
        float p = 0.f;
        if (t < CK) { p = __expf(schunk[t] - m_new); pbuf[t] = p; }
        float ps = p;
        #pragma unroll
        for (int o = 16; o; o >>= 1) ps += __shfl_xor_sync(~0u, ps, o);
        if (lane == 0) redm[wid] = ps;
        __syncthreads();                                   // S4
        float csum = redm[0] + redm[1];
        l = l * scale + csum;
        m = m_new;
        wacc *= scale;

        // wacc[ch-channel] += sum_k p_k * rel[k][ch-channel]
        {
            const float* col = cb + half * 32 * TST + chw;
            const float* pw  = pbuf + half * 32;
            #pragma unroll
            for (int kk = 0; kk < 32; kk++) wacc += pw[kk] * col[kk * TST];
        }
        __syncthreads();                                   // S5: buffer free

        if (ch + 2 < NCH) {
            int nch = ch + 2;
            uint32_t bb = bufu + (uint32_t)(nch & 1) * CK * TST * 4;
            #pragma unroll
            for (int jj = 0; jj < 8; jj++) {
                int idx = jj * 256 + t;
                uint32_t d = bb + (uint32_t)((idx >> 5) * TST + (idx & 31) * 4) * 4;
                CP_ASYNC16(d, rp + nch * (CK * Hz / 4) + idx);
            }
            CP_COMMIT();
        }
    }

    float invl = 1.f / l;
    // rel probs (normalized)
    g_probs[((b * 4 + hr) * Sz + q) * Sz + t] = __expf(sall[t] - m) * invl;

    // reduce wacc halves -> wfin (reuse uvec)
    wpart[t] = wacc;
    __syncthreads();
    if (t < Hz) uvec[t] = wpart[t] + wpart[t + 128];
    __syncthreads();
    // project wfin through Wv_hr (4 thread-groups of 32 channels each)
    if (t < Hz) {
        int c = t & 31, qtr = t >> 5;
        float s2 = 0.f;
        #pragma unroll
        for (int j = 0; j < 32; j++)
            s2 += uvec[qtr * 32 + j] * Wv[(qtr * 32 + j) * Hz + hr * HDz + c];
        wpart[t] = s2;
    }
    __syncthreads();
    if (t < HDz) {
        float w = wpart[t] + wpart[t + 32] + wpart[t + 64] + wpart[t + 96];
        g_ctxbase[(b * Sz + q) * Hz + hr * HDz + t] = w * invl + bv[hr * HDz + t];
    }
}

// ---------------------------------------------------------------------------
// K3: ctx[b,q,h,:] = ctxbase + sum_k probs[b,h,q,k] * Veff_h[b,k,:]
// grid (qt=8, b=8, h=4), 256 threads.
// ---------------------------------------------------------------------------
__global__ void __launch_bounds__(256) ctxv_kernel() {
    int qt = blockIdx.x, b = blockIdx.y, h = blockIdx.z;
    int t = threadIdx.x;
    extern __shared__ float sm3[];
    float* Vs = sm3;                 // 256*33
    float* Ps = sm3 + 256 * 33;      // 32*256

    #pragma unroll
    for (int jj = 0; jj < 8; jj++) {
        int idx = jj * 256 + t;
        int row = idx >> 3, c4 = idx & 7;
        float4 v = *(const float4*)&g_Veff[(b * Sz + row) * Hz + h * HDz + c4 * 4];
        Vs[row * 33 + c4 * 4 + 0] = v.x;
        Vs[row * 33 + c4 * 4 + 1] = v.y;
        Vs[row * 33 + c4 * 4 + 2] = v.z;
        Vs[row * 33 + c4 * 4 + 3] = v.w;
    }
    #pragma unroll
    for (int jj = 0; jj < 8; jj++) {
        int idx = jj * 256 + t;                 // 2048 float4
        int qq = idx >> 6, k4 = idx & 63;
        float4 v = *(const float4*)&g_probs[((b * 4 + h) * Sz + qt * 32 + qq) * Sz + k4 * 4];
        *(float4*)&Ps[qq * 256 + k4 * 4] = v;
    }
    __syncthreads();

    int c = t & 31, q0 = t >> 5;    // each thread: 4 q's (q0, q0+8, q0+16, q0+24)
    float acc0 = 0.f, acc1 = 0.f, acc2 = 0.f, acc3 = 0.f;
    #pragma unroll 8
    for (int k = 0; k < Sz; k++) {
        float v = Vs[k * 33 + c];
        acc0 += Ps[(q0     ) * 256 + k] * v;
        acc1 += Ps[(q0 +  8) * 256 + k] * v;
        acc2 += Ps[(q0 + 16) * 256 + k] * v;
        acc3 += Ps[(q0 + 24) * 256 + k] * v;
    }
    #pragma unroll
    for (int r = 0; r < 4; r++) {
        int q = qt * 32 + q0 + r * 8;
        float a = (r == 0) ? acc0 : (r == 1) ? acc1 : (r == 2) ? acc2 : acc3;
        g_ctx[(b * Sz + q) * Hz + h * HDz + c] =
            g_ctxbase[(b * Sz + q) * Hz + h * HDz + c] + a;
    }
}

// ---------------------------------------------------------------------------
// K4: out = ctx @ Wo + bo. 4 rows per CTA.
// ---------------------------------------------------------------------------
__global__ void out_kernel(const float* __restrict__ Wo,
                           const float* __restrict__ bo,
                           float* __restrict__ out) {
    int r0 = blockIdx.x * 4;
    int j = threadIdx.x;
    __shared__ float xs[4][Hz];
    #pragma unroll
    for (int r = 0; r < 4; r++) xs[r][j] = g_ctx[(r0 + r) * Hz + j];
    __syncthreads();
    float a0 = bo[j], a1 = a0, a2 = a0, a3 = a0;
    #pragma unroll 4
    for (int i = 0; i < Hz; i++) {
        float w = Wo[i * Hz + j];
        a0 += xs[0][i] * w; a1 += xs[1][i] * w;
        a2 += xs[2][i] * w; a3 += xs[3][i] * w;
    }
    out[r0 * Hz + j] = a0;
    out[(r0 + 1) * Hz + j] = a1;
    out[(r0 + 2) * Hz + j] = a2;
    out[(r0 + 3) * Hz + j] = a3;
}

// ---------------------------------------------------------------------------
extern "C" void kernel_launch(void* const* d_in, const int* in_sizes, int n_in,
                              void* d_out, int out_size) {
    const float* X    = (const float*)d_in[0];
    const float* mask = (const float*)d_in[1];
    const float* abs0 = (const float*)d_in[2];
    const float* abs1 = (const float*)d_in[3];
    const float* rel0 = (const float*)d_in[4];
    const float* rel1 = (const float*)d_in[5];
    const float* Wq   = (const float*)d_in[6];
    const float* bq   = (const float*)d_in[7];
    const float* Wk   = (const float*)d_in[8];
    const float* bk   = (const float*)d_in[9];
    const float* Wv   = (const float*)d_in[10];
    const float* bv   = (const float*)d_in[11];
    const float* Wo   = (const float*)d_in[12];
    const float* bo   = (const float*)d_in[13];
    float* out = (float*)d_out;

    size_t relsm  = (size_t)(2 * CK * TST + 256 + 128 + 256 + 64 + 64 + 8 + 4 + 256 + 32) * sizeof(float);
    size_t ctxsm  = (size_t)(256 * 33 + 32 * 256) * sizeof(float);
    static int configured = 0;
    cudaFuncSetAttribute(rel_kernel,  cudaFuncAttributeMaxDynamicSharedMemorySize, (int)relsm);
    cudaFuncSetAttribute(ctxv_kernel, cudaFuncAttributeMaxDynamicSharedMemorySize, (int)ctxsm);
    (void)configured;

    proj_kernel<<<BSz / 2, Hz>>>(X, abs0, abs1, Wq, bq, Wk, bk, Wv, bv);
    dim3 gs(8, Bz, 4);
    sbase_kernel<<<gs, 256>>>(mask);
    dim3 gr(Sz, Bz, 2);
    rel_kernel<<<gr, 256, relsm>>>(rel0, rel1, Wk, Wv, bv);
    ctxv_kernel<<<gs, 256, ctxsm>>>();
    out_kernel<<<BSz / 4, Hz>>>(Wo, bo, out);
}

// round 5
// speedup vs baseline: 2.6666x; 1.5161x over previous
#include <cuda_runtime.h>
#include <cstdint>

#define Bz  8
#define Sz  256
#define Hz  128
#define HDz 32
#define BSz 2048
#define SCALE 0.17677669529663687f   // 1/sqrt(32)
#define TST 132                       // tile row stride (floats): conflict-free LDS.128 phases

// __device__ scratch (allocation-free rule)
__device__ float g_Q[BSz * Hz];
__device__ float g_Keff[BSz * Hz];
__device__ float g_Veff[BSz * Hz];
__device__ float g_sbase[Bz * 4 * Sz * Sz];    // [b][h][q][k]
__device__ float g_probs[Bz * 4 * Sz * Sz];    // abs: normalized; rel: pexp (scaled in ctxv)
__device__ float g_pscale[Bz * 4 * Sz * 2];    // per (b,h,q,half) prob scale
__device__ float g_mred[Bz * 2 * Sz * 2 * 2];  // (m,l) per (b,i,q,half)
__device__ float g_wpart[Bz * 2 * Sz * 2 * Hz];// wacc per (b,i,q,half)[128]
__device__ float g_ctxbase[BSz * Hz];
__device__ float g_ctx[BSz * Hz];

#define CP_ASYNC16(dst, src) \
    asm volatile("cp.async.cg.shared.global [%0], [%1], 16;\n" :: "r"(dst), "l"(src))
#define CP_COMMIT() asm volatile("cp.async.commit_group;\n" ::: "memory")
#define CP_WAIT0()  asm volatile("cp.async.wait_group 0;\n" ::: "memory")

// ---------------------------------------------------------------------------
// K0: projections. 2 rows per CTA, 128 threads.
// ---------------------------------------------------------------------------
__global__ void proj_kernel(const float* __restrict__ X,
                            const float* __restrict__ abs0,
                            const float* __restrict__ abs1,
                            const float* __restrict__ Wq, const float* __restrict__ bq,
                            const float* __restrict__ Wk, const float* __restrict__ bk,
                            const float* __restrict__ Wv, const float* __restrict__ bv) {
    int r0 = blockIdx.x * 2;
    int j  = threadIdx.x;
    __shared__ float xs[2][Hz], a0s[2][Hz], a1s[2][Hz];
    #pragma unroll
    for (int r = 0; r < 2; r++) {
        xs[r][j]  = X[(r0 + r) * Hz + j];
        a0s[r][j] = abs0[(r0 + r) * Hz + j];
        a1s[r][j] = abs1[(r0 + r) * Hz + j];
    }
    __syncthreads();

    float q0 = bq[j], k0 = bk[j], v0 = bv[j];
    float q1 = q0, k1 = k0, v1 = v0;
    #pragma unroll 4
    for (int i = 0; i < Hz; i++) {
        float wq = Wq[i * Hz + j], wk = Wk[i * Hz + j], wv = Wv[i * Hz + j];
        float x0 = xs[0][i], x1 = xs[1][i];
        q0 += x0 * wq; k0 += x0 * wk; v0 += x0 * wv;
        q1 += x1 * wq; k1 += x1 * wk; v1 += x1 * wv;
    }
    if (j < 64) {   // abs-head folds
        float ka0 = bk[j], va0 = bv[j], ka1 = ka0, va1 = va0;
        #pragma unroll 4
        for (int i = 0; i < Hz; i++) {
            float wk = Wk[i * Hz + j], wv = Wv[i * Hz + j];
            float b0 = (j < 32) ? a0s[0][i] : a1s[0][i];
            float b1 = (j < 32) ? a0s[1][i] : a1s[1][i];
            ka0 += b0 * wk; va0 += b0 * wv;
            ka1 += b1 * wk; va1 += b1 * wv;
        }
        k0 += ka0; v0 += va0; k1 += ka1; v1 += va1;
    }
    g_Q[r0 * Hz + j] = q0;        g_Q[(r0 + 1) * Hz + j] = q1;
    g_Keff[r0 * Hz + j] = k0;     g_Keff[(r0 + 1) * Hz + j] = k1;
    g_Veff[r0 * Hz + j] = v0;     g_Veff[(r0 + 1) * Hz + j] = v1;
}

// ---------------------------------------------------------------------------
// K1: sbase[b,h,q,k] = (Q_h[q].Keff_h[k])*SCALE + mask[b,q,k]
// ---------------------------------------------------------------------------
__global__ void __launch_bounds__(256) sbase_kernel(const float* __restrict__ mask) {
    int qt = blockIdx.x, b = blockIdx.y, h = blockIdx.z;
    int t = threadIdx.x;
    __shared__ float Qs[32 * 32];
    __shared__ float ks[256 * 33];

    #pragma unroll
    for (int r = 0; r < 4; r++) {
        int idx = r * 256 + t;
        int qq = idx >> 5, c = idx & 31;
        Qs[idx] = g_Q[(b * Sz + qt * 32 + qq) * Hz + h * HDz + c];
    }
    #pragma unroll
    for (int jj = 0; jj < 8; jj++) {
        int idx = jj * 256 + t;
        int row = idx >> 3, c4 = idx & 7;
        float4 v = *(const float4*)&g_Keff[(b * Sz + row) * Hz + h * HDz + c4 * 4];
        ks[row * 33 + c4 * 4 + 0] = v.x;
        ks[row * 33 + c4 * 4 + 1] = v.y;
        ks[row * 33 + c4 * 4 + 2] = v.z;
        ks[row * 33 + c4 * 4 + 3] = v.w;
    }
    __syncthreads();

    float kr[32];
    #pragma unroll
    for (int c = 0; c < 32; c++) kr[c] = ks[t * 33 + c];

    int qbase = qt * 32;
    #pragma unroll 2
    for (int qq = 0; qq < 32; qq++) {
        float acc = 0.f;
        #pragma unroll
        for (int c = 0; c < 32; c++) acc += Qs[qq * 32 + c] * kr[c];
        int q = qbase + qq;
        g_sbase[((b * 4 + h) * Sz + q) * Sz + t] =
            acc * SCALE + mask[(b * Sz + q) * Sz + t];
    }
}

// ---------------------------------------------------------------------------
// K2: rel split-K. CTA per (q, b, i*2+half); 128 threads (4 warps).
// Warp w owns local keys 32w..32w+31 (lane = one key). All 64KB issued
// upfront; per-warp cp.async wait; scores in registers; ~5 barriers total.
// Outputs per half: pexp (unnormalized), (m,l), wacc[128].
// ---------------------------------------------------------------------------
__global__ void __launch_bounds__(128, 3) rel_kernel(
        const float* __restrict__ rel0, const float* __restrict__ rel1,
        const float* __restrict__ Wk) {
    int q = blockIdx.x, b = blockIdx.y;
    int i = blockIdx.z >> 1, half = blockIdx.z & 1;
    int hr = 2 + i;
    int kbase = half * 128;
    int t = threadIdx.x, lane = t & 31, w = t >> 5;

    extern __shared__ float sm[];
    float* tile = sm;                 // [128][TST]
    float* uvec = sm + 128 * TST;     // 128
    float* kb   = uvec + 128;         // 128
    float* pc   = kb + 128;           // 128
    float* qvr  = pc + 128;           // 32
    float* wm   = qvr + 32;           // 4
    float* wl   = wm + 4;             // 4

    // 1) issue ALL loads (per-warp rows; lane = float4 column)
    const float4* rp4 = (const float4*)(((i == 0) ? rel0 : rel1)
                        + (size_t)(b * Sz + q) * Sz * Hz) + (size_t)kbase * 32;
    uint32_t tileu = (uint32_t)__cvta_generic_to_shared(tile);
    #pragma unroll
    for (int r = 0; r < 32; r++) {
        int row = w * 32 + r;
        uint32_t d = tileu + (uint32_t)(row * TST + lane * 4) * 4;
        CP_ASYNC16(d, rp4 + row * 32 + lane);
    }
    CP_COMMIT();

    // 2) prologue loads (overlap DRAM)
    if (t < 32) qvr[t] = g_Q[(b * Sz + q) * Hz + hr * HDz + t];
    kb[t] = g_sbase[((b * 4 + hr) * Sz + q) * Sz + kbase + t];
    __syncthreads();

    // 3) u = Wk_hr^T q_hr
    {
        float acc = 0.f;
        const float* wrow = Wk + t * Hz + hr * HDz;
        #pragma unroll
        for (int c = 0; c < HDz; c++) acc += wrow[c] * qvr[c];
        uvec[t] = acc;
    }
    __syncthreads();

    // 4) per-warp: wait own rows, compute own 32 scores (row = key = t)
    CP_WAIT0();
    __syncwarp();
    float s;
    {
        const float4* row = (const float4*)&tile[t * TST];
        const float4* u4  = (const float4*)uvec;
        float acc = 0.f;
        #pragma unroll
        for (int j = 0; j < 32; j++) {
            float4 r = row[j], u = u4[j];
            acc += r.x * u.x + r.y * u.y + r.z * u.z + r.w * u.w;
        }
        s = acc * SCALE + kb[t];
    }
    float mw = s;
    #pragma unroll
    for (int o = 16; o; o >>= 1) mw = fmaxf(mw, __shfl_xor_sync(~0u, mw, o));
    if (lane == 0) wm[w] = mw;
    __syncthreads();

    // 5) half-local max, p, half-local sum
    float M = fmaxf(fmaxf(wm[0], wm[1]), fmaxf(wm[2], wm[3]));
    float p = __expf(s - M);
    pc[t] = p;
    float lw = p;
    #pragma unroll
    for (int o = 16; o; o >>= 1) lw += __shfl_xor_sync(~0u, lw, o);
    if (lane == 0) wl[w] = lw;
    __syncthreads();
    float L = wl[0] + wl[1] + wl[2] + wl[3];

    // store pexp (unnormalized wrt this half's M)
    g_probs[((b * 4 + hr) * Sz + q) * Sz + kbase + t] = p;
    if (t == 0) {
        int mi = ((b * 2 + i) * Sz + q) * 2 + half;
        g_mred[mi * 2 + 0] = M;
        g_mred[mi * 2 + 1] = L;
    }

    // 6) wacc[ch] = sum_k pc[k] * tile[k][ch]
    {
        float wacc = 0.f;
        #pragma unroll 8
        for (int k = 0; k < 128; k++)
            wacc += pc[k] * tile[k * TST + t];
        g_wpart[(((b * 2 + i) * Sz + q) * 2 + half) * Hz + t] = wacc;
    }
}

// ---------------------------------------------------------------------------
// K2b: combine. CTA per (q, b, i); 128 threads.
// Merges split-K halves (m,l,wacc), projects w through Wv_hr -> ctxbase,
// writes pscale for both heads, and does the abs-head softmax.
// ---------------------------------------------------------------------------
__global__ void __launch_bounds__(128) combine_kernel(
        const float* __restrict__ Wv, const float* __restrict__ bv) {
    int q = blockIdx.x, b = blockIdx.y, i = blockIdx.z;
    int hr = 2 + i, ha = i;
    int t = threadIdx.x, lane = t & 31, w = t >> 5;

    __shared__ float wfin[Hz];
    __shared__ float wp2[Hz];
    __shared__ float red[4];
    __shared__ float sc2[4];

    int mi = ((b * 2 + i) * Sz + q) * 2;
    float m0 = g_mred[(mi + 0) * 2 + 0], l0 = g_mred[(mi + 0) * 2 + 1];
    float m1 = g_mred[(mi + 1) * 2 + 0], l1 = g_mred[(mi + 1) * 2 + 1];
    float M = fmaxf(m0, m1);
    float c0 = __expf(m0 - M), c1 = __expf(m1 - M);
    float invL = 1.f / (l0 * c0 + l1 * c1);

    // merged w
    wfin[t] = g_wpart[(mi + 0) * Hz + t] * c0 + g_wpart[(mi + 1) * Hz + t] * c1;

    if (t == 0) {
        g_pscale[((b * 4 + hr) * Sz + q) * 2 + 0] = c0 * invL;
        g_pscale[((b * 4 + hr) * Sz + q) * 2 + 1] = c1 * invL;
        g_pscale[((b * 4 + ha) * Sz + q) * 2 + 0] = 1.f;
        g_pscale[((b * 4 + ha) * Sz + q) * 2 + 1] = 1.f;
    }

    // abs-head softmax over 256 (2 values per thread)
    float sa0 = g_sbase[((b * 4 + ha) * Sz + q) * Sz + t];
    float sa1 = g_sbase[((b * 4 + ha) * Sz + q) * Sz + t + 128];
    float mv = fmaxf(sa0, sa1);
    #pragma unroll
    for (int o = 16; o; o >>= 1) mv = fmaxf(mv, __shfl_xor_sync(~0u, mv, o));
    if (lane == 0) red[w] = mv;
    __syncthreads();
    float Ma = fmaxf(fmaxf(red[0], red[1]), fmaxf(red[2], red[3]));
    float p0 = __expf(sa0 - Ma), p1 = __expf(sa1 - Ma);
    float sv = p0 + p1;
    #pragma unroll
    for (int o = 16; o; o >>= 1) sv += __shfl_xor_sync(~0u, sv, o);
    if (lane == 0) sc2[w] = sv;
    __syncthreads();
    float invLa = 1.f / (sc2[0] + sc2[1] + sc2[2] + sc2[3]);
    g_probs[((b * 4 + ha) * Sz + q) * Sz + t]       = p0 * invLa;
    g_probs[((b * 4 + ha) * Sz + q) * Sz + t + 128] = p1 * invLa;
    if (t < HDz) g_ctxbase[(b * Sz + q) * Hz + ha * HDz + t] = 0.f;

    // project wfin through Wv_hr (4 groups of 32 channels)
    {
        int c = t & 31, g = t >> 5;
        float pp = 0.f;
        #pragma unroll
        for (int j = 0; j < 32; j++)
            pp += wfin[g * 32 + j] * Wv[(g * 32 + j) * Hz + hr * HDz + c];
        wp2[t] = pp;
    }
    __syncthreads();
    if (t < HDz) {
        float ww = wp2[t] + wp2[t + 32] + wp2[t + 64] + wp2[t + 96];
        g_ctxbase[(b * Sz + q) * Hz + hr * HDz + t] = ww * invL + bv[hr * HDz + t];
    }
}

// ---------------------------------------------------------------------------
// K3: ctx = ctxbase + probs(scaled) @ Veff. grid (8,8,4), 256 threads.
// ---------------------------------------------------------------------------
__global__ void __launch_bounds__(256) ctxv_kernel() {
    int qt = blockIdx.x, b = blockIdx.y, h = blockIdx.z;
    int t = threadIdx.x;
    extern __shared__ float sm3[];
    float* Vs  = sm3;                  // 256*33
    float* Ps  = sm3 + 256 * 33;       // 32*256
    float* psc = sm3 + 256 * 33 + 32 * 256;  // 64

    if (t < 64) {
        int qq = t >> 1, hh = t & 1;
        psc[t] = g_pscale[((b * 4 + h) * Sz + qt * 32 + qq) * 2 + hh];
    }
    #pragma unroll
    for (int jj = 0; jj < 8; jj++) {
        int idx = jj * 256 + t;
        int row = idx >> 3, c4 = idx & 7;
        float4 v = *(const float4*)&g_Veff[(b * Sz + row) * Hz + h * HDz + c4 * 4];
        Vs[row * 33 + c4 * 4 + 0] = v.x;
        Vs[row * 33 + c4 * 4 + 1] = v.y;
        Vs[row * 33 + c4 * 4 + 2] = v.z;
        Vs[row * 33 + c4 * 4 + 3] = v.w;
    }
    __syncthreads();
    #pragma unroll
    for (int jj = 0; jj < 8; jj++) {
        int idx = jj * 256 + t;
        int qq = idx >> 6, k4 = idx & 63;
        float4 v = *(const float4*)&g_probs[((b * 4 + h) * Sz + qt * 32 + qq) * Sz + k4 * 4];
        float sc = psc[qq * 2 + (k4 >= 32 ? 1 : 0)];
        v.x *= sc; v.y *= sc; v.z *= sc; v.w *= sc;
        *(float4*)&Ps[qq * 256 + k4 * 4] = v;
    }
    __syncthreads();

    int c = t & 31, q0 = t >> 5;
    const float4* Ps4 = (const float4*)Ps;
    float acc0 = 0.f, acc1 = 0.f, acc2 = 0.f, acc3 = 0.f;
    #pragma unroll 4
    for (int k4 = 0; k4 < 64; k4++) {
        float v0 = Vs[(k4 * 4 + 0) * 33 + c];
        float v1 = Vs[(k4 * 4 + 1) * 33 + c];
        float v2 = Vs[(k4 * 4 + 2) * 33 + c];
        float v3 = Vs[(k4 * 4 + 3) * 33 + c];
        float4 P0 = Ps4[(q0     ) * 64 + k4];
        float4 P1 = Ps4[(q0 +  8) * 64 + k4];
        float4 P2 = Ps4[(q0 + 16) * 64 + k4];
        float4 P3 = Ps4[(q0 + 24) * 64 + k4];
        acc0 += P0.x * v0 + P0.y * v1 + P0.z * v2 + P0.w * v3;
        acc1 += P1.x * v0 + P1.y * v1 + P1.z * v2 + P1.w * v3;
        acc2 += P2.x * v0 + P2.y * v1 + P2.z * v2 + P2.w * v3;
        acc3 += P3.x * v0 + P3.y * v1 + P3.z * v2 + P3.w * v3;
    }
    #pragma unroll
    for (int r = 0; r < 4; r++) {
        int q = qt * 32 + q0 + r * 8;
        float a = (r == 0) ? acc0 : (r == 1) ? acc1 : (r == 2) ? acc2 : acc3;
        g_ctx[(b * Sz + q) * Hz + h * HDz + c] =
            g_ctxbase[(b * Sz + q) * Hz + h * HDz + c] + a;
    }
}

// ---------------------------------------------------------------------------
// K4: out = ctx @ Wo + bo. 4 rows per CTA.
// ---------------------------------------------------------------------------
__global__ void out_kernel(const float* __restrict__ Wo,
                           const float* __restrict__ bo,
                           float* __restrict__ out) {
    int r0 = blockIdx.x * 4;
    int j = threadIdx.x;
    __shared__ float xs[4][Hz];
    #pragma unroll
    for (int r = 0; r < 4; r++) xs[r][j] = g_ctx[(r0 + r) * Hz + j];
    __syncthreads();
    float a0 = bo[j], a1 = a0, a2 = a0, a3 = a0;
    #pragma unroll 4
    for (int i = 0; i < Hz; i++) {
        float w = Wo[i * Hz + j];
        a0 += xs[0][i] * w; a1 += xs[1][i] * w;
        a2 += xs[2][i] * w; a3 += xs[3][i] * w;
    }
    out[r0 * Hz + j] = a0;
    out[(r0 + 1) * Hz + j] = a1;
    out[(r0 + 2) * Hz + j] = a2;
    out[(r0 + 3) * Hz + j] = a3;
}

// ---------------------------------------------------------------------------
extern "C" void kernel_launch(void* const* d_in, const int* in_sizes, int n_in,
                              void* d_out, int out_size) {
    const float* X    = (const float*)d_in[0];
    const float* mask = (const float*)d_in[1];
    const float* abs0 = (const float*)d_in[2];
    const float* abs1 = (const float*)d_in[3];
    const float* rel0 = (const float*)d_in[4];
    const float* rel1 = (const float*)d_in[5];
    const float* Wq   = (const float*)d_in[6];
    const float* bq   = (const float*)d_in[7];
    const float* Wk   = (const float*)d_in[8];
    const float* bk   = (const float*)d_in[9];
    const float* Wv   = (const float*)d_in[10];
    const float* bv   = (const float*)d_in[11];
    const float* Wo   = (const float*)d_in[12];
    const float* bo   = (const float*)d_in[13];
    float* out = (float*)d_out;

    size_t relsm = (size_t)(128 * TST + 128 + 128 + 128 + 32 + 4 + 4) * sizeof(float);
    size_t ctxsm = (size_t)(256 * 33 + 32 * 256 + 64) * sizeof(float);
    cudaFuncSetAttribute(rel_kernel,  cudaFuncAttributeMaxDynamicSharedMemorySize, (int)relsm);
    cudaFuncSetAttribute(ctxv_kernel, cudaFuncAttributeMaxDynamicSharedMemorySize, (int)ctxsm);

    proj_kernel<<<BSz / 2, Hz>>>(X, abs0, abs1, Wq, bq, Wk, bk, Wv, bv);
    dim3 gs(8, Bz, 4);
    sbase_kernel<<<gs, 256>>>(mask);
    dim3 gr(Sz, Bz, 4);             // z = i*2 + half
    rel_kernel<<<gr, 128, relsm>>>(rel0, rel1, Wk);
    dim3 gc(Sz, Bz, 2);
    combine_kernel<<<gc, 128>>>(Wv, bv);
    ctxv_kernel<<<gs, 256, ctxsm>>>();
    out_kernel<<<BSz / 4, Hz>>>(Wo, bo, out);
}